// round 11
// baseline (speedup 1.0000x reference)
#include <cuda_runtime.h>
#include <cuda_fp16.h>
#include <math.h>

#define NN 50000
#define EE 1600000
#define DD 128
#define ET (EE + NN)
#define SCAN_BLK 98          // ceil(50000 / 512)

// ---------------- scratch (static device globals; no allocation) ------------
__device__ __half g_bufA[NN * DD];   // layer input activations (fp16)
__device__ __half g_bufH[NN * DD];   // h = A @ W (fp16 for the gather)
__device__ __half g_Wt[3 * DD * DD]; // per-layer W, fp16, transposed [n][k]
__device__ float  g_s[NN];           // h . a_src
__device__ float  g_d[NN];           // h . a_dst
__device__ int    g_count[NN];
__device__ int    g_rowptr[NN + 1];
__device__ int    g_cursor[NN];
__device__ int    g_col[ET];         // CSR (by dst) source indices
__device__ int    g_part[SCAN_BLK];  // per-block scan partials

// ---------------- CSR build --------------------------------------------------
__global__ void init_count_kernel() {
    int i = blockIdx.x * blockDim.x + threadIdx.x;
    if (i < NN) g_count[i] = 1;   // self loop
}

// 4 edges per thread: independent REDs in flight
__global__ void hist_kernel(const int* __restrict__ dst) {
    int base = (blockIdx.x * blockDim.x + threadIdx.x) * 4;
    if (base + 3 < EE) {
        int4 t4 = *(const int4*)&dst[base];
        atomicAdd(&g_count[t4.x], 1);
        atomicAdd(&g_count[t4.y], 1);
        atomicAdd(&g_count[t4.z], 1);
        atomicAdd(&g_count[t4.w], 1);
    } else {
        for (int i = base; i < EE && i < base + 4; i++)
            atomicAdd(&g_count[dst[i]], 1);
    }
}

__global__ void bscan_kernel() {
    __shared__ int wsum[16];
    int tid = threadIdx.x, lane = tid & 31, wid = tid >> 5;
    int i = blockIdx.x * 512 + tid;
    int v = (i < NN) ? g_count[i] : 0;
    int x = v;
    #pragma unroll
    for (int o = 1; o < 32; o <<= 1) {
        int y = __shfl_up_sync(0xffffffffu, x, o);
        if (lane >= o) x += y;
    }
    if (lane == 31) wsum[wid] = x;
    __syncthreads();
    if (wid == 0 && lane < 16) {
        int w = wsum[lane];
        int xx = w;
        #pragma unroll
        for (int o = 1; o < 16; o <<= 1) {
            int y = __shfl_up_sync(0xffffu, xx, o);
            if (lane >= o) xx += y;
        }
        wsum[lane] = xx - w;
    }
    __syncthreads();
    int incl = x + wsum[wid];
    if (i < NN) g_rowptr[i] = incl - v;
    if (tid == 511) g_part[blockIdx.x] = incl;
}

__global__ void badd_kernel() {
    __shared__ int parts[SCAN_BLK];
    __shared__ int offs;
    int tid = threadIdx.x;
    if (tid < SCAN_BLK) parts[tid] = g_part[tid];
    __syncthreads();
    if (tid == 0) {
        int o = 0;
        for (int b = 0; b < (int)blockIdx.x; b++) o += parts[b];
        offs = o;
        if (blockIdx.x == gridDim.x - 1) {
            int tot = o;
            for (int b = blockIdx.x; b < SCAN_BLK; b++) tot += parts[b];
            g_rowptr[NN] = tot;
        }
    }
    __syncthreads();
    int i = blockIdx.x * 512 + tid;
    if (i < NN) {
        int r = g_rowptr[i] + offs;
        g_rowptr[i] = r;
        g_cursor[i] = r;
    }
}

// 4 edges per thread: 4 independent ATOMG chains in flight
__global__ void scatter_kernel(const int* __restrict__ src, const int* __restrict__ dst) {
    int base = (blockIdx.x * blockDim.x + threadIdx.x) * 4;
    if (base + 3 < EE) {
        int4 s4 = *(const int4*)&src[base];
        int4 t4 = *(const int4*)&dst[base];
        int p0 = atomicAdd(&g_cursor[t4.x], 1);
        int p1 = atomicAdd(&g_cursor[t4.y], 1);
        int p2 = atomicAdd(&g_cursor[t4.z], 1);
        int p3 = atomicAdd(&g_cursor[t4.w], 1);
        g_col[p0] = s4.x;
        g_col[p1] = s4.y;
        g_col[p2] = s4.z;
        g_col[p3] = s4.w;
    } else {
        for (int i = base; i < ET && i < base + 4; i++) {
            int s, t;
            if (i < EE) { s = src[i]; t = dst[i]; }
            else        { s = i - EE; t = s; }
            int pos = atomicAdd(&g_cursor[t], 1);
            g_col[pos] = s;
        }
    }
}

// ---------------- W prep: fp32 [k][n] -> fp16 transposed [n][k] ---------------
__global__ void wprep_kernel(const float* __restrict__ W, int layer) {
    int j = blockIdx.x * blockDim.x + threadIdx.x;
    if (j >= DD * DD) return;
    int k = j >> 7, n = j & 127;
    g_Wt[layer * DD * DD + n * DD + k] = __float2half(W[j]);
}

// ---------------- expmap0 (writes fp16 activations) ---------------------------
__global__ void expmap_kernel(const float* __restrict__ x) {
    int gid = blockIdx.x * blockDim.x + threadIdx.x;
    int row = gid >> 5, lane = gid & 31;
    if (row >= NN) return;
    float4 v = ((const float4*)x)[row * 32 + lane];
    float ss = v.x * v.x + v.y * v.y + v.z * v.z + v.w * v.w;
    #pragma unroll
    for (int o = 16; o; o >>= 1) ss += __shfl_xor_sync(0xffffffffu, ss, o);
    float n = sqrtf(ss);
    n = fmaxf(n, 1e-15f);
    float sc = tanhf(n) / n;
    __half2 h0 = __floats2half2_rn(v.x * sc, v.y * sc);
    __half2 h1 = __floats2half2_rn(v.z * sc, v.w * sc);
    uint2 st;
    st.x = *(unsigned int*)&h0;
    st.y = *(unsigned int*)&h1;
    ((uint2*)g_bufA)[row * 32 + lane] = st;
}

// ---------------- tensor-core GEMM: H = A @ W + fused s/d epilogue -----------
// 256 threads (8 warps), tile 128x128. ldmatrix.x4 for A and B fragments.
#define KS 136

__device__ __forceinline__ void mma16816(float* c, unsigned a0, unsigned a1,
                                         unsigned a2, unsigned a3,
                                         unsigned b0, unsigned b1) {
    asm volatile(
        "mma.sync.aligned.m16n8k16.row.col.f32.f16.f16.f32 "
        "{%0,%1,%2,%3}, {%4,%5,%6,%7}, {%8,%9}, {%0,%1,%2,%3};"
        : "+f"(c[0]), "+f"(c[1]), "+f"(c[2]), "+f"(c[3])
        : "r"(a0), "r"(a1), "r"(a2), "r"(a3), "r"(b0), "r"(b1));
}

__device__ __forceinline__ void ldsm_x4(unsigned& r0, unsigned& r1,
                                        unsigned& r2, unsigned& r3, unsigned addr) {
    asm volatile("ldmatrix.sync.aligned.m8n8.x4.shared.b16 {%0,%1,%2,%3}, [%4];"
        : "=r"(r0), "=r"(r1), "=r"(r2), "=r"(r3) : "r"(addr));
}

__global__ void __launch_bounds__(256, 2)
gemm_kernel(const __half* __restrict__ A, const __half* __restrict__ Wg,
            const float* __restrict__ avs, const float* __restrict__ avd) {
    extern __shared__ char smraw[];
    __half* Wts = (__half*)smraw;                    // [128][KS]
    __half* As  = Wts + 128 * KS;                    // [128][KS]
    float*  ass = (float*)(As + 128 * KS);           // [128]
    float*  ads = ass + 128;                         // [128]
    int tid = threadIdx.x;
    int row0 = blockIdx.x * 128;

    for (int i = tid; i < 128 * 16; i += 256) {
        int n = i >> 4, kc = i & 15;
        *(uint4*)&Wts[n * KS + kc * 8] = ((const uint4*)Wg)[i];
    }
    for (int i = tid; i < 128 * 16; i += 256) {
        int r = i >> 4, kc = i & 15;
        int row = row0 + r;
        uint4 v = (row < NN) ? ((const uint4*)A)[row * 16 + kc]
                             : make_uint4(0u, 0u, 0u, 0u);
        *(uint4*)&As[r * KS + kc * 8] = v;
    }
    if (tid < 128) { ass[tid] = avs[tid]; ads[tid] = avd[tid]; }
    __syncthreads();

    int w = tid >> 5, lane = tid & 31;
    int gid = lane >> 2, tig = lane & 3;
    int rA = w * 16 + gid;
    int rB = rA + 8;

    // ldmatrix lane addresses (bytes)
    unsigned asBase = (unsigned)__cvta_generic_to_shared(As);
    unsigned wtBase = (unsigned)__cvta_generic_to_shared(Wts);
    // A x4: lanes 0-15 -> rows rbase+(l&15) @k0, lanes 16-31 -> same rows @k0+8
    unsigned aAddr = asBase + ((w * 16 + (lane & 15)) * KS + (lane >> 4) * 8) * 2;
    // B x4 (nt pair p): lanes 0-7 rows p*16+0..7 @k0, 8-15 same @k0+8,
    //                   16-23 rows p*16+8..15 @k0, 24-31 same @k0+8
    unsigned bAddr = wtBase + (((lane >> 4) * 8 + (lane & 7)) * KS + ((lane >> 3) & 1) * 8) * 2;

    float c[16][4];
    #pragma unroll
    for (int nt = 0; nt < 16; nt++)
        #pragma unroll
        for (int j = 0; j < 4; j++) c[nt][j] = 0.f;

    #pragma unroll
    for (int ks = 0; ks < 8; ks++) {
        unsigned koff = ks * 32;         // 16 halves = 32 bytes
        unsigned a0, a1, a2, a3;
        ldsm_x4(a0, a1, a2, a3, aAddr + koff);
        #pragma unroll
        for (int p = 0; p < 8; p++) {
            unsigned b0, b1, b2, b3;
            ldsm_x4(b0, b1, b2, b3, bAddr + p * (16 * KS * 2) + koff);
            mma16816(c[2 * p],     a0, a1, a2, a3, b0, b1);
            mma16816(c[2 * p + 1], a0, a1, a2, a3, b2, b3);
        }
    }

    int rowA = row0 + rA, rowB = row0 + rB;
    float s0 = 0.f, s1 = 0.f, d0 = 0.f, d1 = 0.f;
    #pragma unroll
    for (int nt = 0; nt < 16; nt++) {
        int col = nt * 8 + 2 * tig;
        float2 as2 = *(const float2*)&ass[col];
        float2 ad2 = *(const float2*)&ads[col];
        s0 += c[nt][0] * as2.x + c[nt][1] * as2.y;
        d0 += c[nt][0] * ad2.x + c[nt][1] * ad2.y;
        s1 += c[nt][2] * as2.x + c[nt][3] * as2.y;
        d1 += c[nt][2] * ad2.x + c[nt][3] * ad2.y;
        if (rowA < NN) {
            __half2 h = __floats2half2_rn(c[nt][0], c[nt][1]);
            *(unsigned*)&g_bufH[rowA * 128 + col] = *(unsigned*)&h;
        }
        if (rowB < NN) {
            __half2 h = __floats2half2_rn(c[nt][2], c[nt][3]);
            *(unsigned*)&g_bufH[rowB * 128 + col] = *(unsigned*)&h;
        }
    }
    #pragma unroll
    for (int o = 1; o <= 2; o <<= 1) {
        s0 += __shfl_xor_sync(0xffffffffu, s0, o);
        d0 += __shfl_xor_sync(0xffffffffu, d0, o);
        s1 += __shfl_xor_sync(0xffffffffu, s1, o);
        d1 += __shfl_xor_sync(0xffffffffu, d1, o);
    }
    if (tig == 0) {
        if (rowA < NN) { g_s[rowA] = s0; g_d[rowA] = d0; }
        if (rowB < NN) { g_s[rowB] = s1; g_d[rowB] = d1; }
    }
}

// ---------------- aggregation helpers -----------------------------------------
__device__ __forceinline__ void gather_acc2(const __half* __restrict__ H,
                                            const int* sb, const float* eb,
                                            int cn, int half, int fl,
                                            float* acc8) {
    int j = 0;
    for (; j + 8 <= cn; j += 8) {
        uint4 hv[4];
        float al[4];
        #pragma unroll
        for (int u = 0; u < 4; u++) {
            int idx = j + 2 * u + half;
            int sn = sb[idx];
            al[u] = eb[idx];
            hv[u] = __ldcg(((const uint4*)(H + sn * 128)) + fl);
        }
        #pragma unroll
        for (int u = 0; u < 4; u++) {
            const __half2* p = (const __half2*)&hv[u];
            #pragma unroll
            for (int q = 0; q < 4; q++) {
                float2 f = __half22float2(p[q]);
                acc8[2 * q + 0] = fmaf(al[u], f.x, acc8[2 * q + 0]);
                acc8[2 * q + 1] = fmaf(al[u], f.y, acc8[2 * q + 1]);
            }
        }
    }
    for (; j < cn; j += 2) {
        int idx = j + half;
        int sn = sb[idx];
        float al = eb[idx];
        uint4 hv = __ldcg(((const uint4*)(H + sn * 128)) + fl);
        const __half2* p = (const __half2*)&hv;
        #pragma unroll
        for (int q = 0; q < 4; q++) {
            float2 f = __half22float2(p[q]);
            acc8[2 * q + 0] = fmaf(al, f.x, acc8[2 * q + 0]);
            acc8[2 * q + 1] = fmaf(al, f.y, acc8[2 * q + 1]);
        }
    }
}

// ---------------- per-node attention aggregation (1 warp / node, static) -----
__global__ void __launch_bounds__(256, 5)
agg_kernel(const __half* __restrict__ H, const float* __restrict__ sarr,
           const float* __restrict__ darr, const float* __restrict__ bias,
           float* __restrict__ outF, __half* __restrict__ outH, int act) {
    __shared__ float ebuf[8][130];
    __shared__ int   sbuf[8][130];
    int lane = threadIdx.x & 31, ws = threadIdx.x >> 5;
    int node = (blockIdx.x * blockDim.x + threadIdx.x) >> 5;
    if (node >= NN) return;

    int beg = g_rowptr[node], end = g_rowptr[node + 1];
    int deg = end - beg;
    float di = darr[node];
    float* eb = ebuf[ws];
    int*   sb = sbuf[ws];
    int half = lane >> 4, fl = lane & 15;

    float m = -1e30f, den = 0.f;
    bool small = (deg <= 128);

    if (small) {
        for (int j = lane; j < deg; j += 32) {
            int sn = g_col[beg + j];
            float e = __ldg(&sarr[sn]) + di;
            e = e > 0.f ? e : 0.2f * e;
            sb[j] = sn;
            eb[j] = e;
            float nm = fmaxf(m, e);
            den = den * __expf(m - nm) + __expf(e - nm);
            m = nm;
        }
    } else {
        for (int j = beg + lane; j < end; j += 32) {
            float e = __ldg(&sarr[g_col[j]]) + di;
            e = e > 0.f ? e : 0.2f * e;
            float nm = fmaxf(m, e);
            den = den * __expf(m - nm) + __expf(e - nm);
            m = nm;
        }
    }
    #pragma unroll
    for (int o = 16; o; o >>= 1) {
        float m2 = __shfl_xor_sync(0xffffffffu, m, o);
        float d2 = __shfl_xor_sync(0xffffffffu, den, o);
        float nm = fmaxf(m, m2);
        den = den * __expf(m - nm) + d2 * __expf(m2 - nm);
        m = nm;
    }
    float inv = 1.f / den;

    float acc8[8];
    #pragma unroll
    for (int q = 0; q < 8; q++) acc8[q] = 0.f;

    if (small) {
        for (int j = lane; j < deg; j += 32)
            eb[j] = __expf(eb[j] - m) * inv;
        if (lane == 0 && (deg & 1)) { eb[deg] = 0.f; sb[deg] = 0; }
        __syncwarp();
        gather_acc2(H, sb, eb, (deg + 1) & ~1, half, fl, acc8);
        __syncwarp();
    } else {
        for (int cb = beg; cb < end; cb += 128) {
            int cn = min(128, end - cb);
            for (int j = lane; j < cn; j += 32) {
                int sn = g_col[cb + j];
                float e = __ldg(&sarr[sn]) + di;
                e = e > 0.f ? e : 0.2f * e;
                sb[j] = sn;
                eb[j] = __expf(e - m) * inv;
            }
            if (lane == 0 && (cn & 1)) { eb[cn] = 0.f; sb[cn] = 0; }
            __syncwarp();
            gather_acc2(H, sb, eb, (cn + 1) & ~1, half, fl, acc8);
            __syncwarp();
        }
    }

    #pragma unroll
    for (int q = 0; q < 8; q++)
        acc8[q] += __shfl_xor_sync(0xffffffffu, acc8[q], 16);

    if (half == 0) {
        float4 b0 = ((const float4*)bias)[fl * 2];
        float4 b1 = ((const float4*)bias)[fl * 2 + 1];
        acc8[0] += b0.x; acc8[1] += b0.y; acc8[2] += b0.z; acc8[3] += b0.w;
        acc8[4] += b1.x; acc8[5] += b1.y; acc8[6] += b1.z; acc8[7] += b1.w;
        if (act) {
            #pragma unroll
            for (int q = 0; q < 8; q++) acc8[q] = 2.f * tanhf(acc8[q]);
            __half2 h0 = __floats2half2_rn(acc8[0], acc8[1]);
            __half2 h1 = __floats2half2_rn(acc8[2], acc8[3]);
            __half2 h2 = __floats2half2_rn(acc8[4], acc8[5]);
            __half2 h3 = __floats2half2_rn(acc8[6], acc8[7]);
            uint4 st;
            st.x = *(unsigned*)&h0; st.y = *(unsigned*)&h1;
            st.z = *(unsigned*)&h2; st.w = *(unsigned*)&h3;
            ((uint4*)(outH + node * 128))[fl] = st;
        } else {
            float4 o0 = make_float4(acc8[0], acc8[1], acc8[2], acc8[3]);
            float4 o1 = make_float4(acc8[4], acc8[5], acc8[6], acc8[7]);
            ((float4*)(outF + node * 128))[fl * 2] = o0;
            ((float4*)(outF + node * 128))[fl * 2 + 1] = o1;
        }
    }
}

// ---------------- launch ------------------------------------------------------
extern "C" void kernel_launch(void* const* d_in, const int* in_sizes, int n_in,
                              void* d_out, int out_size) {
    const float* x   = (const float*)d_in[0];
    const int*   ei  = (const int*)d_in[1];
    const int*   esrc = ei;
    const int*   edst = ei + EE;
    const float* W1  = (const float*)d_in[2];
    const float* a1s = (const float*)d_in[3];
    const float* a1d = (const float*)d_in[4];
    const float* b1  = (const float*)d_in[5];
    const float* W2  = (const float*)d_in[6];
    const float* a2s = (const float*)d_in[7];
    const float* a2d = (const float*)d_in[8];
    const float* b2  = (const float*)d_in[9];
    const float* W3  = (const float*)d_in[10];
    const float* a3s = (const float*)d_in[11];
    const float* a3d = (const float*)d_in[12];
    const float* b3  = (const float*)d_in[13];
    float* out = (float*)d_out;

    float *pS, *pD;
    __half *pA, *pH, *pW;
    cudaGetSymbolAddress((void**)&pA, g_bufA);
    cudaGetSymbolAddress((void**)&pH, g_bufH);
    cudaGetSymbolAddress((void**)&pW, g_Wt);
    cudaGetSymbolAddress((void**)&pS, g_s);
    cudaGetSymbolAddress((void**)&pD, g_d);

    const int SMEM = (128 * KS + 128 * KS) * 2 + 2 * 128 * 4;   // ~70.7 KB
    cudaFuncSetAttribute(gemm_kernel, cudaFuncAttributeMaxDynamicSharedMemorySize, SMEM);

    int gemm_blocks = (NN + 127) / 128;      // 391
    int agg_blocks  = (NN + 7) / 8;
    int wblocks = (DD * DD + 255) / 256;
    int hist_blocks = (EE / 4 + 255) / 256;
    int scat_blocks = ((ET + 3) / 4 + 255) / 256;

    // slot 4 = gemm_kernel (ncu capture)
    init_count_kernel<<<(NN + 255) / 256, 256>>>();             // 1
    expmap_kernel<<<(NN * 32 + 255) / 256, 256>>>(x);           // 2
    wprep_kernel<<<wblocks, 256>>>(W1, 0);                      // 3
    gemm_kernel<<<gemm_blocks, 256, SMEM>>>(pA, pW, a1s, a1d);  // 4 (ncu)
    wprep_kernel<<<wblocks, 256>>>(W2, 1);                      // 5
    wprep_kernel<<<wblocks, 256>>>(W3, 2);                      // 6
    hist_kernel<<<hist_blocks, 256>>>(edst);                    // 7
    bscan_kernel<<<SCAN_BLK, 512>>>();                          // 8
    badd_kernel<<<SCAN_BLK, 512>>>();                           // 9
    scatter_kernel<<<scat_blocks, 256>>>(esrc, edst);           // 10
    agg_kernel<<<agg_blocks, 256>>>(pH, pS, pD, b1, nullptr, pA, 1);
    gemm_kernel<<<gemm_blocks, 256, SMEM>>>(pA, pW + DD * DD, a2s, a2d);
    agg_kernel<<<agg_blocks, 256>>>(pH, pS, pD, b2, nullptr, pA, 1);
    gemm_kernel<<<gemm_blocks, 256, SMEM>>>(pA, pW + 2 * DD * DD, a3s, a3d);
    agg_kernel<<<agg_blocks, 256>>>(pH, pS, pD, b3, out, nullptr, 0);
}

// round 12
// speedup vs baseline: 1.0327x; 1.0327x over previous
#include <cuda_runtime.h>
#include <cuda_fp16.h>
#include <math.h>

#define NN 50000
#define EE 1600000
#define DD 128
#define ET (EE + NN)
#define SCAN_BLK 98          // ceil(50000 / 512)

// ---------------- scratch (static device globals; no allocation) ------------
__device__ __half g_bufA[NN * DD];   // layer input activations (fp16)
__device__ __half g_bufH[NN * DD];   // h = A @ W (fp16 for the gather)
__device__ __half g_Wt[3 * DD * DD]; // per-layer W, fp16, transposed [n][k]
__device__ float  g_s[NN];           // h . a_src
__device__ float  g_d[NN];           // h . a_dst
__device__ int    g_count[NN];
__device__ int    g_rowptr[NN + 1];
__device__ int    g_cursor[NN];
__device__ int    g_col[ET];         // CSR (by dst) source indices
__device__ int    g_part[SCAN_BLK];  // per-block scan partials

// ---------------- CSR build --------------------------------------------------
__global__ void init_count_kernel() {
    int i = blockIdx.x * blockDim.x + threadIdx.x;
    if (i < NN) g_count[i] = 1;   // self loop
}

__global__ void hist_kernel(const int* __restrict__ dst) {
    int base = (blockIdx.x * blockDim.x + threadIdx.x) * 4;
    if (base + 3 < EE) {
        int4 t4 = *(const int4*)&dst[base];
        atomicAdd(&g_count[t4.x], 1);
        atomicAdd(&g_count[t4.y], 1);
        atomicAdd(&g_count[t4.z], 1);
        atomicAdd(&g_count[t4.w], 1);
    } else {
        for (int i = base; i < EE && i < base + 4; i++)
            atomicAdd(&g_count[dst[i]], 1);
    }
}

__global__ void bscan_kernel() {
    __shared__ int wsum[16];
    int tid = threadIdx.x, lane = tid & 31, wid = tid >> 5;
    int i = blockIdx.x * 512 + tid;
    int v = (i < NN) ? g_count[i] : 0;
    int x = v;
    #pragma unroll
    for (int o = 1; o < 32; o <<= 1) {
        int y = __shfl_up_sync(0xffffffffu, x, o);
        if (lane >= o) x += y;
    }
    if (lane == 31) wsum[wid] = x;
    __syncthreads();
    if (wid == 0 && lane < 16) {
        int w = wsum[lane];
        int xx = w;
        #pragma unroll
        for (int o = 1; o < 16; o <<= 1) {
            int y = __shfl_up_sync(0xffffu, xx, o);
            if (lane >= o) xx += y;
        }
        wsum[lane] = xx - w;
    }
    __syncthreads();
    int incl = x + wsum[wid];
    if (i < NN) g_rowptr[i] = incl - v;
    if (tid == 511) g_part[blockIdx.x] = incl;
}

__global__ void badd_kernel() {
    __shared__ int parts[SCAN_BLK];
    __shared__ int offs;
    int tid = threadIdx.x;
    if (tid < SCAN_BLK) parts[tid] = g_part[tid];
    __syncthreads();
    if (tid == 0) {
        int o = 0;
        for (int b = 0; b < (int)blockIdx.x; b++) o += parts[b];
        offs = o;
        if (blockIdx.x == gridDim.x - 1) {
            int tot = o;
            for (int b = blockIdx.x; b < SCAN_BLK; b++) tot += parts[b];
            g_rowptr[NN] = tot;
        }
    }
    __syncthreads();
    int i = blockIdx.x * 512 + tid;
    if (i < NN) {
        int r = g_rowptr[i] + offs;
        g_rowptr[i] = r;
        g_cursor[i] = r;
    }
}

__global__ void scatter_kernel(const int* __restrict__ src, const int* __restrict__ dst) {
    int base = (blockIdx.x * blockDim.x + threadIdx.x) * 4;
    if (base + 3 < EE) {
        int4 s4 = *(const int4*)&src[base];
        int4 t4 = *(const int4*)&dst[base];
        int p0 = atomicAdd(&g_cursor[t4.x], 1);
        int p1 = atomicAdd(&g_cursor[t4.y], 1);
        int p2 = atomicAdd(&g_cursor[t4.z], 1);
        int p3 = atomicAdd(&g_cursor[t4.w], 1);
        g_col[p0] = s4.x;
        g_col[p1] = s4.y;
        g_col[p2] = s4.z;
        g_col[p3] = s4.w;
    } else {
        for (int i = base; i < ET && i < base + 4; i++) {
            int s, t;
            if (i < EE) { s = src[i]; t = dst[i]; }
            else        { s = i - EE; t = s; }
            int pos = atomicAdd(&g_cursor[t], 1);
            g_col[pos] = s;
        }
    }
}

// ---------------- W prep: fp32 [k][n] -> fp16 transposed [n][k] ---------------
__global__ void wprep_kernel(const float* __restrict__ W, int layer) {
    int j = blockIdx.x * blockDim.x + threadIdx.x;
    if (j >= DD * DD) return;
    int k = j >> 7, n = j & 127;
    g_Wt[layer * DD * DD + n * DD + k] = __float2half(W[j]);
}

// ---------------- expmap0 (writes fp16 activations) ---------------------------
__global__ void expmap_kernel(const float* __restrict__ x) {
    int gid = blockIdx.x * blockDim.x + threadIdx.x;
    int row = gid >> 5, lane = gid & 31;
    if (row >= NN) return;
    float4 v = ((const float4*)x)[row * 32 + lane];
    float ss = v.x * v.x + v.y * v.y + v.z * v.z + v.w * v.w;
    #pragma unroll
    for (int o = 16; o; o >>= 1) ss += __shfl_xor_sync(0xffffffffu, ss, o);
    float n = sqrtf(ss);
    n = fmaxf(n, 1e-15f);
    float sc = tanhf(n) / n;
    __half2 h0 = __floats2half2_rn(v.x * sc, v.y * sc);
    __half2 h1 = __floats2half2_rn(v.z * sc, v.w * sc);
    uint2 st;
    st.x = *(unsigned int*)&h0;
    st.y = *(unsigned int*)&h1;
    ((uint2*)g_bufA)[row * 32 + lane] = st;
}

// ---------------- tensor-core GEMM: H = A @ W + fused s/d epilogue -----------
// 512 threads (16 warps), tile 128x128. Warp = 16-row slab x 64-col half.
// c[8][4] = 32 accumulator regs -> 2 blocks/SM = 32 warps resident.
#define KS 136

__device__ __forceinline__ void mma16816(float* c, unsigned a0, unsigned a1,
                                         unsigned a2, unsigned a3,
                                         unsigned b0, unsigned b1) {
    asm volatile(
        "mma.sync.aligned.m16n8k16.row.col.f32.f16.f16.f32 "
        "{%0,%1,%2,%3}, {%4,%5,%6,%7}, {%8,%9}, {%0,%1,%2,%3};"
        : "+f"(c[0]), "+f"(c[1]), "+f"(c[2]), "+f"(c[3])
        : "r"(a0), "r"(a1), "r"(a2), "r"(a3), "r"(b0), "r"(b1));
}

__global__ void __launch_bounds__(512, 2)
gemm_kernel(const __half* __restrict__ A, const __half* __restrict__ Wg,
            const float* __restrict__ avs, const float* __restrict__ avd) {
    extern __shared__ char smraw[];
    __half* Wts = (__half*)smraw;                    // [128][KS]
    __half* As  = Wts + 128 * KS;                    // [128][KS]
    float*  ass = (float*)(As + 128 * KS);           // [128]
    float*  ads = ass + 128;                         // [128]
    float*  sred = ads + 128;                        // [256] (half, row)
    float*  dred = sred + 256;                       // [256]
    int tid = threadIdx.x;
    int row0 = blockIdx.x * 128;

    for (int i = tid; i < 128 * 16; i += 512) {
        int n = i >> 4, kc = i & 15;
        *(uint4*)&Wts[n * KS + kc * 8] = ((const uint4*)Wg)[i];
    }
    for (int i = tid; i < 128 * 16; i += 512) {
        int r = i >> 4, kc = i & 15;
        int row = row0 + r;
        uint4 v = (row < NN) ? ((const uint4*)A)[row * 16 + kc]
                             : make_uint4(0u, 0u, 0u, 0u);
        *(uint4*)&As[r * KS + kc * 8] = v;
    }
    if (tid < 128) { ass[tid] = avs[tid]; ads[tid] = avd[tid]; }
    __syncthreads();

    int w = tid >> 5, lane = tid & 31;
    int gid = lane >> 2, tig = lane & 3;
    int slab = w >> 1, h = w & 1;
    int rA = slab * 16 + gid;        // local rows 0..127
    int rB = rA + 8;
    int nc0 = h * 64;                // column half

    float c[8][4];
    #pragma unroll
    for (int nt = 0; nt < 8; nt++)
        #pragma unroll
        for (int j = 0; j < 4; j++) c[nt][j] = 0.f;

    #pragma unroll
    for (int ks = 0; ks < 8; ks++) {
        int k0 = ks * 16;
        unsigned a0 = *(const unsigned*)&As[rA * KS + k0 + 2 * tig];
        unsigned a1 = *(const unsigned*)&As[rB * KS + k0 + 2 * tig];
        unsigned a2 = *(const unsigned*)&As[rA * KS + k0 + 2 * tig + 8];
        unsigned a3 = *(const unsigned*)&As[rB * KS + k0 + 2 * tig + 8];
        #pragma unroll
        for (int nt = 0; nt < 8; nt++) {
            const __half* bp = &Wts[(nc0 + nt * 8 + gid) * KS + k0 + 2 * tig];
            unsigned b0 = *(const unsigned*)bp;
            unsigned b1 = *(const unsigned*)(bp + 8);
            mma16816(c[nt], a0, a1, a2, a3, b0, b1);
        }
    }

    int rowA = row0 + rA, rowB = row0 + rB;
    float s0 = 0.f, s1 = 0.f, d0 = 0.f, d1 = 0.f;
    #pragma unroll
    for (int nt = 0; nt < 8; nt++) {
        int col = nc0 + nt * 8 + 2 * tig;
        float2 as2 = *(const float2*)&ass[col];
        float2 ad2 = *(const float2*)&ads[col];
        s0 += c[nt][0] * as2.x + c[nt][1] * as2.y;
        d0 += c[nt][0] * ad2.x + c[nt][1] * ad2.y;
        s1 += c[nt][2] * as2.x + c[nt][3] * as2.y;
        d1 += c[nt][2] * ad2.x + c[nt][3] * ad2.y;
        if (rowA < NN) {
            __half2 hh = __floats2half2_rn(c[nt][0], c[nt][1]);
            *(unsigned*)&g_bufH[rowA * 128 + col] = *(unsigned*)&hh;
        }
        if (rowB < NN) {
            __half2 hh = __floats2half2_rn(c[nt][2], c[nt][3]);
            *(unsigned*)&g_bufH[rowB * 128 + col] = *(unsigned*)&hh;
        }
    }
    #pragma unroll
    for (int o = 1; o <= 2; o <<= 1) {
        s0 += __shfl_xor_sync(0xffffffffu, s0, o);
        d0 += __shfl_xor_sync(0xffffffffu, d0, o);
        s1 += __shfl_xor_sync(0xffffffffu, s1, o);
        d1 += __shfl_xor_sync(0xffffffffu, d1, o);
    }
    if (tig == 0) {
        sred[h * 128 + rA] = s0; dred[h * 128 + rA] = d0;
        sred[h * 128 + rB] = s1; dred[h * 128 + rB] = d1;
    }
    __syncthreads();
    if (tid < 128) {
        int row = row0 + tid;
        if (row < NN) {
            g_s[row] = sred[tid] + sred[128 + tid];
            g_d[row] = dred[tid] + dred[128 + tid];
        }
    }
}

// ---------------- aggregation helpers -----------------------------------------
__device__ __forceinline__ void gather_acc2(const __half* __restrict__ H,
                                            const int* sb, const float* eb,
                                            int cn, int half, int fl,
                                            float* acc8) {
    int j = 0;
    for (; j + 8 <= cn; j += 8) {
        uint4 hv[4];
        float al[4];
        #pragma unroll
        for (int u = 0; u < 4; u++) {
            int idx = j + 2 * u + half;
            int sn = sb[idx];
            al[u] = eb[idx];
            hv[u] = __ldcg(((const uint4*)(H + sn * 128)) + fl);
        }
        #pragma unroll
        for (int u = 0; u < 4; u++) {
            const __half2* p = (const __half2*)&hv[u];
            #pragma unroll
            for (int q = 0; q < 4; q++) {
                float2 f = __half22float2(p[q]);
                acc8[2 * q + 0] = fmaf(al[u], f.x, acc8[2 * q + 0]);
                acc8[2 * q + 1] = fmaf(al[u], f.y, acc8[2 * q + 1]);
            }
        }
    }
    for (; j < cn; j += 2) {
        int idx = j + half;
        int sn = sb[idx];
        float al = eb[idx];
        uint4 hv = __ldcg(((const uint4*)(H + sn * 128)) + fl);
        const __half2* p = (const __half2*)&hv;
        #pragma unroll
        for (int q = 0; q < 4; q++) {
            float2 f = __half22float2(p[q]);
            acc8[2 * q + 0] = fmaf(al, f.x, acc8[2 * q + 0]);
            acc8[2 * q + 1] = fmaf(al, f.y, acc8[2 * q + 1]);
        }
    }
}

// ---------------- per-node attention aggregation (1 warp / node, static) -----
__global__ void __launch_bounds__(256, 5)
agg_kernel(const __half* __restrict__ H, const float* __restrict__ sarr,
           const float* __restrict__ darr, const float* __restrict__ bias,
           float* __restrict__ outF, __half* __restrict__ outH, int act) {
    __shared__ float ebuf[8][130];
    __shared__ int   sbuf[8][130];
    int lane = threadIdx.x & 31, ws = threadIdx.x >> 5;
    int node = (blockIdx.x * blockDim.x + threadIdx.x) >> 5;
    if (node >= NN) return;

    int beg = g_rowptr[node], end = g_rowptr[node + 1];
    int deg = end - beg;
    float di = darr[node];
    float* eb = ebuf[ws];
    int*   sb = sbuf[ws];
    int half = lane >> 4, fl = lane & 15;

    float m = -1e30f, den = 0.f;
    bool small = (deg <= 128);

    if (small) {
        for (int j = lane; j < deg; j += 32) {
            int sn = g_col[beg + j];
            float e = __ldg(&sarr[sn]) + di;
            e = e > 0.f ? e : 0.2f * e;
            sb[j] = sn;
            eb[j] = e;
            float nm = fmaxf(m, e);
            den = den * __expf(m - nm) + __expf(e - nm);
            m = nm;
        }
    } else {
        for (int j = beg + lane; j < end; j += 32) {
            float e = __ldg(&sarr[g_col[j]]) + di;
            e = e > 0.f ? e : 0.2f * e;
            float nm = fmaxf(m, e);
            den = den * __expf(m - nm) + __expf(e - nm);
            m = nm;
        }
    }
    #pragma unroll
    for (int o = 16; o; o >>= 1) {
        float m2 = __shfl_xor_sync(0xffffffffu, m, o);
        float d2 = __shfl_xor_sync(0xffffffffu, den, o);
        float nm = fmaxf(m, m2);
        den = den * __expf(m - nm) + d2 * __expf(m2 - nm);
        m = nm;
    }
    float inv = 1.f / den;

    float acc8[8];
    #pragma unroll
    for (int q = 0; q < 8; q++) acc8[q] = 0.f;

    if (small) {
        for (int j = lane; j < deg; j += 32)
            eb[j] = __expf(eb[j] - m) * inv;
        if (lane == 0 && (deg & 1)) { eb[deg] = 0.f; sb[deg] = 0; }
        __syncwarp();
        gather_acc2(H, sb, eb, (deg + 1) & ~1, half, fl, acc8);
        __syncwarp();
    } else {
        for (int cb = beg; cb < end; cb += 128) {
            int cn = min(128, end - cb);
            for (int j = lane; j < cn; j += 32) {
                int sn = g_col[cb + j];
                float e = __ldg(&sarr[sn]) + di;
                e = e > 0.f ? e : 0.2f * e;
                sb[j] = sn;
                eb[j] = __expf(e - m) * inv;
            }
            if (lane == 0 && (cn & 1)) { eb[cn] = 0.f; sb[cn] = 0; }
            __syncwarp();
            gather_acc2(H, sb, eb, (cn + 1) & ~1, half, fl, acc8);
            __syncwarp();
        }
    }

    #pragma unroll
    for (int q = 0; q < 8; q++)
        acc8[q] += __shfl_xor_sync(0xffffffffu, acc8[q], 16);

    if (half == 0) {
        float4 b0 = ((const float4*)bias)[fl * 2];
        float4 b1 = ((const float4*)bias)[fl * 2 + 1];
        acc8[0] += b0.x; acc8[1] += b0.y; acc8[2] += b0.z; acc8[3] += b0.w;
        acc8[4] += b1.x; acc8[5] += b1.y; acc8[6] += b1.z; acc8[7] += b1.w;
        if (act) {
            #pragma unroll
            for (int q = 0; q < 8; q++) acc8[q] = 2.f * tanhf(acc8[q]);
            __half2 h0 = __floats2half2_rn(acc8[0], acc8[1]);
            __half2 h1 = __floats2half2_rn(acc8[2], acc8[3]);
            __half2 h2 = __floats2half2_rn(acc8[4], acc8[5]);
            __half2 h3 = __floats2half2_rn(acc8[6], acc8[7]);
            uint4 st;
            st.x = *(unsigned*)&h0; st.y = *(unsigned*)&h1;
            st.z = *(unsigned*)&h2; st.w = *(unsigned*)&h3;
            ((uint4*)(outH + node * 128))[fl] = st;
        } else {
            float4 o0 = make_float4(acc8[0], acc8[1], acc8[2], acc8[3]);
            float4 o1 = make_float4(acc8[4], acc8[5], acc8[6], acc8[7]);
            ((float4*)(outF + node * 128))[fl * 2] = o0;
            ((float4*)(outF + node * 128))[fl * 2 + 1] = o1;
        }
    }
}

// ---------------- launch ------------------------------------------------------
extern "C" void kernel_launch(void* const* d_in, const int* in_sizes, int n_in,
                              void* d_out, int out_size) {
    const float* x   = (const float*)d_in[0];
    const int*   ei  = (const int*)d_in[1];
    const int*   esrc = ei;
    const int*   edst = ei + EE;
    const float* W1  = (const float*)d_in[2];
    const float* a1s = (const float*)d_in[3];
    const float* a1d = (const float*)d_in[4];
    const float* b1  = (const float*)d_in[5];
    const float* W2  = (const float*)d_in[6];
    const float* a2s = (const float*)d_in[7];
    const float* a2d = (const float*)d_in[8];
    const float* b2  = (const float*)d_in[9];
    const float* W3  = (const float*)d_in[10];
    const float* a3s = (const float*)d_in[11];
    const float* a3d = (const float*)d_in[12];
    const float* b3  = (const float*)d_in[13];
    float* out = (float*)d_out;

    float *pS, *pD;
    __half *pA, *pH, *pW;
    cudaGetSymbolAddress((void**)&pA, g_bufA);
    cudaGetSymbolAddress((void**)&pH, g_bufH);
    cudaGetSymbolAddress((void**)&pW, g_Wt);
    cudaGetSymbolAddress((void**)&pS, g_s);
    cudaGetSymbolAddress((void**)&pD, g_d);

    const int SMEM = (128 * KS + 128 * KS) * 2 + 2 * 128 * 4 + 2 * 256 * 4; // ~72.7 KB
    cudaFuncSetAttribute(gemm_kernel, cudaFuncAttributeMaxDynamicSharedMemorySize, SMEM);

    int gemm_blocks = (NN + 127) / 128;      // 391
    int agg_blocks  = (NN + 7) / 8;
    int wblocks = (DD * DD + 255) / 256;
    int hist_blocks = (EE / 4 + 255) / 256;
    int scat_blocks = ((ET + 3) / 4 + 255) / 256;

    // slot 4 = gemm_kernel (ncu capture)
    init_count_kernel<<<(NN + 255) / 256, 256>>>();             // 1
    expmap_kernel<<<(NN * 32 + 255) / 256, 256>>>(x);           // 2
    wprep_kernel<<<wblocks, 256>>>(W1, 0);                      // 3
    gemm_kernel<<<gemm_blocks, 512, SMEM>>>(pA, pW, a1s, a1d);  // 4 (ncu)
    wprep_kernel<<<wblocks, 256>>>(W2, 1);                      // 5
    wprep_kernel<<<wblocks, 256>>>(W3, 2);                      // 6
    hist_kernel<<<hist_blocks, 256>>>(edst);                    // 7
    bscan_kernel<<<SCAN_BLK, 512>>>();                          // 8
    badd_kernel<<<SCAN_BLK, 512>>>();                           // 9
    scatter_kernel<<<scat_blocks, 256>>>(esrc, edst);           // 10
    agg_kernel<<<agg_blocks, 256>>>(pH, pS, pD, b1, nullptr, pA, 1);
    gemm_kernel<<<gemm_blocks, 512, SMEM>>>(pA, pW + DD * DD, a2s, a2d);
    agg_kernel<<<agg_blocks, 256>>>(pH, pS, pD, b2, nullptr, pA, 1);
    gemm_kernel<<<gemm_blocks, 512, SMEM>>>(pA, pW + 2 * DD * DD, a3s, a3d);
    agg_kernel<<<agg_blocks, 256>>>(pH, pS, pD, b3, out, nullptr, 0);
}

// round 13
// speedup vs baseline: 1.0348x; 1.0020x over previous
#include <cuda_runtime.h>
#include <cuda_fp16.h>
#include <math.h>

#define NN 50000
#define EE 1600000
#define DD 128
#define ET (EE + NN)
#define SCAN_BLK 98          // ceil(50000 / 512)

// ---------------- scratch (static device globals; no allocation) ------------
__device__ __half g_bufA[NN * DD];   // layer input activations (fp16)
__device__ __half g_bufH[NN * DD];   // h = A @ W (fp16 for the gather)
__device__ __half g_Wt[3 * DD * DD]; // per-layer W, fp16, transposed [n][k]
__device__ float  g_s[NN];           // h . a_src
__device__ float  g_d[NN];           // h . a_dst
__device__ int    g_count[NN];
__device__ int    g_rowptr[NN + 1];
__device__ int    g_cursor[NN];
__device__ int    g_col[ET];         // CSR (by dst) source indices
__device__ int    g_part[SCAN_BLK];  // per-block scan partials

// ---------------- CSR build --------------------------------------------------
__global__ void init_count_kernel() {
    int i = blockIdx.x * blockDim.x + threadIdx.x;
    if (i < NN) g_count[i] = 1;   // self loop
}

__global__ void hist_kernel(const int* __restrict__ dst) {
    int base = (blockIdx.x * blockDim.x + threadIdx.x) * 4;
    if (base + 3 < EE) {
        int4 t4 = *(const int4*)&dst[base];
        atomicAdd(&g_count[t4.x], 1);
        atomicAdd(&g_count[t4.y], 1);
        atomicAdd(&g_count[t4.z], 1);
        atomicAdd(&g_count[t4.w], 1);
    } else {
        for (int i = base; i < EE && i < base + 4; i++)
            atomicAdd(&g_count[dst[i]], 1);
    }
}

__global__ void bscan_kernel() {
    __shared__ int wsum[16];
    int tid = threadIdx.x, lane = tid & 31, wid = tid >> 5;
    int i = blockIdx.x * 512 + tid;
    int v = (i < NN) ? g_count[i] : 0;
    int x = v;
    #pragma unroll
    for (int o = 1; o < 32; o <<= 1) {
        int y = __shfl_up_sync(0xffffffffu, x, o);
        if (lane >= o) x += y;
    }
    if (lane == 31) wsum[wid] = x;
    __syncthreads();
    if (wid == 0 && lane < 16) {
        int w = wsum[lane];
        int xx = w;
        #pragma unroll
        for (int o = 1; o < 16; o <<= 1) {
            int y = __shfl_up_sync(0xffffu, xx, o);
            if (lane >= o) xx += y;
        }
        wsum[lane] = xx - w;
    }
    __syncthreads();
    int incl = x + wsum[wid];
    if (i < NN) g_rowptr[i] = incl - v;
    if (tid == 511) g_part[blockIdx.x] = incl;
}

__global__ void badd_kernel() {
    __shared__ int parts[SCAN_BLK];
    __shared__ int offs;
    int tid = threadIdx.x;
    if (tid < SCAN_BLK) parts[tid] = g_part[tid];
    __syncthreads();
    if (tid == 0) {
        int o = 0;
        for (int b = 0; b < (int)blockIdx.x; b++) o += parts[b];
        offs = o;
        if (blockIdx.x == gridDim.x - 1) {
            int tot = o;
            for (int b = blockIdx.x; b < SCAN_BLK; b++) tot += parts[b];
            g_rowptr[NN] = tot;
        }
    }
    __syncthreads();
    int i = blockIdx.x * 512 + tid;
    if (i < NN) {
        int r = g_rowptr[i] + offs;
        g_rowptr[i] = r;
        g_cursor[i] = r;
    }
}

__global__ void scatter_kernel(const int* __restrict__ src, const int* __restrict__ dst) {
    int base = (blockIdx.x * blockDim.x + threadIdx.x) * 4;
    if (base + 3 < EE) {
        int4 s4 = *(const int4*)&src[base];
        int4 t4 = *(const int4*)&dst[base];
        int p0 = atomicAdd(&g_cursor[t4.x], 1);
        int p1 = atomicAdd(&g_cursor[t4.y], 1);
        int p2 = atomicAdd(&g_cursor[t4.z], 1);
        int p3 = atomicAdd(&g_cursor[t4.w], 1);
        g_col[p0] = s4.x;
        g_col[p1] = s4.y;
        g_col[p2] = s4.z;
        g_col[p3] = s4.w;
    } else {
        for (int i = base; i < ET && i < base + 4; i++) {
            int s, t;
            if (i < EE) { s = src[i]; t = dst[i]; }
            else        { s = i - EE; t = s; }
            int pos = atomicAdd(&g_cursor[t], 1);
            g_col[pos] = s;
        }
    }
}

// ---------------- W prep: fp32 [k][n] -> fp16 transposed [n][k] ---------------
__global__ void wprep_kernel(const float* __restrict__ W, int layer) {
    int j = blockIdx.x * blockDim.x + threadIdx.x;
    if (j >= DD * DD) return;
    int k = j >> 7, n = j & 127;
    g_Wt[layer * DD * DD + n * DD + k] = __float2half(W[j]);
}

// ---------------- expmap0 (writes fp16 activations) ---------------------------
__global__ void expmap_kernel(const float* __restrict__ x) {
    int gid = blockIdx.x * blockDim.x + threadIdx.x;
    int row = gid >> 5, lane = gid & 31;
    if (row >= NN) return;
    float4 v = ((const float4*)x)[row * 32 + lane];
    float ss = v.x * v.x + v.y * v.y + v.z * v.z + v.w * v.w;
    #pragma unroll
    for (int o = 16; o; o >>= 1) ss += __shfl_xor_sync(0xffffffffu, ss, o);
    float n = sqrtf(ss);
    n = fmaxf(n, 1e-15f);
    float sc = tanhf(n) / n;
    __half2 h0 = __floats2half2_rn(v.x * sc, v.y * sc);
    __half2 h1 = __floats2half2_rn(v.z * sc, v.w * sc);
    uint2 st;
    st.x = *(unsigned int*)&h0;
    st.y = *(unsigned int*)&h1;
    ((uint2*)g_bufA)[row * 32 + lane] = st;
}

// ---------------- tensor-core GEMM: H = A @ W + fused s/d epilogue -----------
// 512 threads (16 warps), tile 128x128. Warp = 16-row slab x 64-col half.
#define KS 136

__device__ __forceinline__ void mma16816(float* c, unsigned a0, unsigned a1,
                                         unsigned a2, unsigned a3,
                                         unsigned b0, unsigned b1) {
    asm volatile(
        "mma.sync.aligned.m16n8k16.row.col.f32.f16.f16.f32 "
        "{%0,%1,%2,%3}, {%4,%5,%6,%7}, {%8,%9}, {%0,%1,%2,%3};"
        : "+f"(c[0]), "+f"(c[1]), "+f"(c[2]), "+f"(c[3])
        : "r"(a0), "r"(a1), "r"(a2), "r"(a3), "r"(b0), "r"(b1));
}

__global__ void __launch_bounds__(512, 2)
gemm_kernel(const __half* __restrict__ A, const __half* __restrict__ Wg,
            const float* __restrict__ avs, const float* __restrict__ avd) {
    extern __shared__ char smraw[];
    __half* Wts = (__half*)smraw;                    // [128][KS]
    __half* As  = Wts + 128 * KS;                    // [128][KS]
    float*  ass = (float*)(As + 128 * KS);           // [128]
    float*  ads = ass + 128;                         // [128]
    float*  sred = ads + 128;                        // [256]
    float*  dred = sred + 256;                       // [256]
    int tid = threadIdx.x;
    int row0 = blockIdx.x * 128;

    for (int i = tid; i < 128 * 16; i += 512) {
        int n = i >> 4, kc = i & 15;
        *(uint4*)&Wts[n * KS + kc * 8] = ((const uint4*)Wg)[i];
    }
    for (int i = tid; i < 128 * 16; i += 512) {
        int r = i >> 4, kc = i & 15;
        int row = row0 + r;
        uint4 v = (row < NN) ? ((const uint4*)A)[row * 16 + kc]
                             : make_uint4(0u, 0u, 0u, 0u);
        *(uint4*)&As[r * KS + kc * 8] = v;
    }
    if (tid < 128) { ass[tid] = avs[tid]; ads[tid] = avd[tid]; }
    __syncthreads();

    int w = tid >> 5, lane = tid & 31;
    int gid = lane >> 2, tig = lane & 3;
    int slab = w >> 1, h = w & 1;
    int rA = slab * 16 + gid;
    int rB = rA + 8;
    int nc0 = h * 64;

    float c[8][4];
    #pragma unroll
    for (int nt = 0; nt < 8; nt++)
        #pragma unroll
        for (int j = 0; j < 4; j++) c[nt][j] = 0.f;

    #pragma unroll
    for (int ks = 0; ks < 8; ks++) {
        int k0 = ks * 16;
        unsigned a0 = *(const unsigned*)&As[rA * KS + k0 + 2 * tig];
        unsigned a1 = *(const unsigned*)&As[rB * KS + k0 + 2 * tig];
        unsigned a2 = *(const unsigned*)&As[rA * KS + k0 + 2 * tig + 8];
        unsigned a3 = *(const unsigned*)&As[rB * KS + k0 + 2 * tig + 8];
        #pragma unroll
        for (int nt = 0; nt < 8; nt++) {
            const __half* bp = &Wts[(nc0 + nt * 8 + gid) * KS + k0 + 2 * tig];
            unsigned b0 = *(const unsigned*)bp;
            unsigned b1 = *(const unsigned*)(bp + 8);
            mma16816(c[nt], a0, a1, a2, a3, b0, b1);
        }
    }

    int rowA = row0 + rA, rowB = row0 + rB;
    float s0 = 0.f, s1 = 0.f, d0 = 0.f, d1 = 0.f;
    #pragma unroll
    for (int nt = 0; nt < 8; nt++) {
        int col = nc0 + nt * 8 + 2 * tig;
        float2 as2 = *(const float2*)&ass[col];
        float2 ad2 = *(const float2*)&ads[col];
        s0 += c[nt][0] * as2.x + c[nt][1] * as2.y;
        d0 += c[nt][0] * ad2.x + c[nt][1] * ad2.y;
        s1 += c[nt][2] * as2.x + c[nt][3] * as2.y;
        d1 += c[nt][2] * ad2.x + c[nt][3] * ad2.y;
        if (rowA < NN) {
            __half2 hh = __floats2half2_rn(c[nt][0], c[nt][1]);
            *(unsigned*)&g_bufH[rowA * 128 + col] = *(unsigned*)&hh;
        }
        if (rowB < NN) {
            __half2 hh = __floats2half2_rn(c[nt][2], c[nt][3]);
            *(unsigned*)&g_bufH[rowB * 128 + col] = *(unsigned*)&hh;
        }
    }
    #pragma unroll
    for (int o = 1; o <= 2; o <<= 1) {
        s0 += __shfl_xor_sync(0xffffffffu, s0, o);
        d0 += __shfl_xor_sync(0xffffffffu, d0, o);
        s1 += __shfl_xor_sync(0xffffffffu, s1, o);
        d1 += __shfl_xor_sync(0xffffffffu, d1, o);
    }
    if (tig == 0) {
        sred[h * 128 + rA] = s0; dred[h * 128 + rA] = d0;
        sred[h * 128 + rB] = s1; dred[h * 128 + rB] = d1;
    }
    __syncthreads();
    if (tid < 128) {
        int row = row0 + tid;
        if (row < NN) {
            g_s[row] = sred[tid] + sred[128 + tid];
            g_d[row] = dred[tid] + dred[128 + tid];
        }
    }
}

// ---------------- per-node attention aggregation: SINGLE PASS ----------------
// No max-subtraction (logits bounded, fp32-safe): out = sum w_j h_j / sum w_j.
// 1 warp/node; per 32-edge chunk each lane computes one weight, then pair-steps
// broadcast (sn, w) via shfl; 16 lanes gather each H row as uint4 (fp16x8).
__global__ void __launch_bounds__(256, 5)
agg_kernel(const __half* __restrict__ H, const float* __restrict__ sarr,
           const float* __restrict__ darr, const float* __restrict__ bias,
           float* __restrict__ outF, __half* __restrict__ outH, int act) {
    int lane = threadIdx.x & 31;
    int node = (blockIdx.x * blockDim.x + threadIdx.x) >> 5;
    if (node >= NN) return;

    int beg = g_rowptr[node], end = g_rowptr[node + 1];
    float di = darr[node];
    int half = lane >> 4, fl = lane & 15;

    float acc8[8];
    #pragma unroll
    for (int q = 0; q < 8; q++) acc8[q] = 0.f;
    float denp = 0.f;

    for (int cb = beg; cb < end; cb += 32) {
        int idx = cb + lane;
        int sn_l = 0;
        float w_l = 0.f;
        if (idx < end) {
            sn_l = g_col[idx];
            float e = __ldg(&sarr[sn_l]) + di;
            e = e > 0.f ? e : 0.2f * e;
            w_l = __expf(e);
        }
        denp += w_l;
        int cn = min(32, end - cb);

        int u = 0;
        for (; u + 8 <= cn; u += 8) {       // 4 pairs = 8 edges, batched
            uint4 hv[4];
            float al[4];
            #pragma unroll
            for (int p = 0; p < 4; p++) {
                int srcl = u + 2 * p + half;
                int sn = __shfl_sync(0xffffffffu, sn_l, srcl);
                al[p]  = __shfl_sync(0xffffffffu, w_l, srcl);
                hv[p]  = __ldcg(((const uint4*)(H + sn * 128)) + fl);
            }
            #pragma unroll
            for (int p = 0; p < 4; p++) {
                const __half2* hp = (const __half2*)&hv[p];
                #pragma unroll
                for (int q = 0; q < 4; q++) {
                    float2 f = __half22float2(hp[q]);
                    acc8[2 * q + 0] = fmaf(al[p], f.x, acc8[2 * q + 0]);
                    acc8[2 * q + 1] = fmaf(al[p], f.y, acc8[2 * q + 1]);
                }
            }
        }
        for (; u < cn; u += 2) {             // leftover pairs (w=0 pads tails)
            int srcl = u + half;
            int sn  = __shfl_sync(0xffffffffu, sn_l, srcl);
            float al = __shfl_sync(0xffffffffu, w_l, srcl);
            uint4 hv = __ldcg(((const uint4*)(H + sn * 128)) + fl);
            const __half2* hp = (const __half2*)&hv;
            #pragma unroll
            for (int q = 0; q < 4; q++) {
                float2 f = __half22float2(hp[q]);
                acc8[2 * q + 0] = fmaf(al, f.x, acc8[2 * q + 0]);
                acc8[2 * q + 1] = fmaf(al, f.y, acc8[2 * q + 1]);
            }
        }
    }

    // reduce den over all 32 lanes; merge the two edge-halves of acc8
    #pragma unroll
    for (int o = 16; o; o >>= 1)
        denp += __shfl_xor_sync(0xffffffffu, denp, o);
    #pragma unroll
    for (int q = 0; q < 8; q++)
        acc8[q] += __shfl_xor_sync(0xffffffffu, acc8[q], 16);

    if (half == 0) {
        float inv = 1.f / denp;
        float4 b0 = ((const float4*)bias)[fl * 2];
        float4 b1 = ((const float4*)bias)[fl * 2 + 1];
        acc8[0] = fmaf(acc8[0], inv, b0.x);
        acc8[1] = fmaf(acc8[1], inv, b0.y);
        acc8[2] = fmaf(acc8[2], inv, b0.z);
        acc8[3] = fmaf(acc8[3], inv, b0.w);
        acc8[4] = fmaf(acc8[4], inv, b1.x);
        acc8[5] = fmaf(acc8[5], inv, b1.y);
        acc8[6] = fmaf(acc8[6], inv, b1.z);
        acc8[7] = fmaf(acc8[7], inv, b1.w);
        if (act) {
            #pragma unroll
            for (int q = 0; q < 8; q++) acc8[q] = 2.f * tanhf(acc8[q]);
            __half2 h0 = __floats2half2_rn(acc8[0], acc8[1]);
            __half2 h1 = __floats2half2_rn(acc8[2], acc8[3]);
            __half2 h2 = __floats2half2_rn(acc8[4], acc8[5]);
            __half2 h3 = __floats2half2_rn(acc8[6], acc8[7]);
            uint4 st;
            st.x = *(unsigned*)&h0; st.y = *(unsigned*)&h1;
            st.z = *(unsigned*)&h2; st.w = *(unsigned*)&h3;
            ((uint4*)(outH + node * 128))[fl] = st;
        } else {
            float4 o0 = make_float4(acc8[0], acc8[1], acc8[2], acc8[3]);
            float4 o1 = make_float4(acc8[4], acc8[5], acc8[6], acc8[7]);
            ((float4*)(outF + node * 128))[fl * 2] = o0;
            ((float4*)(outF + node * 128))[fl * 2 + 1] = o1;
        }
    }
}

// ---------------- launch ------------------------------------------------------
extern "C" void kernel_launch(void* const* d_in, const int* in_sizes, int n_in,
                              void* d_out, int out_size) {
    const float* x   = (const float*)d_in[0];
    const int*   ei  = (const int*)d_in[1];
    const int*   esrc = ei;
    const int*   edst = ei + EE;
    const float* W1  = (const float*)d_in[2];
    const float* a1s = (const float*)d_in[3];
    const float* a1d = (const float*)d_in[4];
    const float* b1  = (const float*)d_in[5];
    const float* W2  = (const float*)d_in[6];
    const float* a2s = (const float*)d_in[7];
    const float* a2d = (const float*)d_in[8];
    const float* b2  = (const float*)d_in[9];
    const float* W3  = (const float*)d_in[10];
    const float* a3s = (const float*)d_in[11];
    const float* a3d = (const float*)d_in[12];
    const float* b3  = (const float*)d_in[13];
    float* out = (float*)d_out;

    float *pS, *pD;
    __half *pA, *pH, *pW;
    cudaGetSymbolAddress((void**)&pA, g_bufA);
    cudaGetSymbolAddress((void**)&pH, g_bufH);
    cudaGetSymbolAddress((void**)&pW, g_Wt);
    cudaGetSymbolAddress((void**)&pS, g_s);
    cudaGetSymbolAddress((void**)&pD, g_d);

    const int SMEM = (128 * KS + 128 * KS) * 2 + 2 * 128 * 4 + 2 * 256 * 4; // ~72.7 KB
    cudaFuncSetAttribute(gemm_kernel, cudaFuncAttributeMaxDynamicSharedMemorySize, SMEM);

    int gemm_blocks = (NN + 127) / 128;      // 391
    int agg_blocks  = (NN + 7) / 8;
    int wblocks = (DD * DD + 255) / 256;
    int hist_blocks = (EE / 4 + 255) / 256;
    int scat_blocks = ((ET + 3) / 4 + 255) / 256;

    // slot 4 = gemm_kernel (ncu capture)
    init_count_kernel<<<(NN + 255) / 256, 256>>>();             // 1
    expmap_kernel<<<(NN * 32 + 255) / 256, 256>>>(x);           // 2
    wprep_kernel<<<wblocks, 256>>>(W1, 0);                      // 3
    gemm_kernel<<<gemm_blocks, 512, SMEM>>>(pA, pW, a1s, a1d);  // 4 (ncu)
    wprep_kernel<<<wblocks, 256>>>(W2, 1);                      // 5
    wprep_kernel<<<wblocks, 256>>>(W3, 2);                      // 6
    hist_kernel<<<hist_blocks, 256>>>(edst);                    // 7
    bscan_kernel<<<SCAN_BLK, 512>>>();                          // 8
    badd_kernel<<<SCAN_BLK, 512>>>();                           // 9
    scatter_kernel<<<scat_blocks, 256>>>(esrc, edst);           // 10
    agg_kernel<<<agg_blocks, 256>>>(pH, pS, pD, b1, nullptr, pA, 1);
    gemm_kernel<<<gemm_blocks, 512, SMEM>>>(pA, pW + DD * DD, a2s, a2d);
    agg_kernel<<<agg_blocks, 256>>>(pH, pS, pD, b2, nullptr, pA, 1);
    gemm_kernel<<<gemm_blocks, 512, SMEM>>>(pA, pW + 2 * DD * DD, a3s, a3d);
    agg_kernel<<<agg_blocks, 256>>>(pH, pS, pD, b3, out, nullptr, 0);
}

// round 14
// speedup vs baseline: 1.0728x; 1.0368x over previous
#include <cuda_runtime.h>
#include <cuda_fp16.h>
#include <math.h>

#define NN 50000
#define EE 1600000
#define DD 128
#define ET (EE + NN)
#define SCAN_BLK 98          // ceil(50000 / 512)

// ---------------- scratch (static device globals; no allocation) ------------
__device__ __half g_bufA[NN * DD];   // layer input activations (fp16)
__device__ __half g_bufH[NN * DD];   // h = A @ W (fp16 for the gather)
__device__ __half g_Wt[3 * DD * DD]; // per-layer W, fp16, transposed [n][k]
__device__ float  g_s[NN];           // h . a_src
__device__ float  g_d[NN];           // h . a_dst
__device__ int    g_count[NN];
__device__ int    g_rowptr[NN + 1];
__device__ int    g_cursor[NN];
__device__ int    g_col[ET];         // CSR (by dst) source indices
__device__ int    g_part[SCAN_BLK];  // per-block scan partials

// ---------------- CSR build --------------------------------------------------
__global__ void init_count_kernel() {
    int i = blockIdx.x * blockDim.x + threadIdx.x;
    if (i < NN) g_count[i] = 1;   // self loop
}

__global__ void hist_kernel(const int* __restrict__ dst) {
    int base = (blockIdx.x * blockDim.x + threadIdx.x) * 4;
    if (base + 3 < EE) {
        int4 t4 = *(const int4*)&dst[base];
        atomicAdd(&g_count[t4.x], 1);
        atomicAdd(&g_count[t4.y], 1);
        atomicAdd(&g_count[t4.z], 1);
        atomicAdd(&g_count[t4.w], 1);
    } else {
        for (int i = base; i < EE && i < base + 4; i++)
            atomicAdd(&g_count[dst[i]], 1);
    }
}

__global__ void bscan_kernel() {
    __shared__ int wsum[16];
    int tid = threadIdx.x, lane = tid & 31, wid = tid >> 5;
    int i = blockIdx.x * 512 + tid;
    int v = (i < NN) ? g_count[i] : 0;
    int x = v;
    #pragma unroll
    for (int o = 1; o < 32; o <<= 1) {
        int y = __shfl_up_sync(0xffffffffu, x, o);
        if (lane >= o) x += y;
    }
    if (lane == 31) wsum[wid] = x;
    __syncthreads();
    if (wid == 0 && lane < 16) {
        int w = wsum[lane];
        int xx = w;
        #pragma unroll
        for (int o = 1; o < 16; o <<= 1) {
            int y = __shfl_up_sync(0xffffu, xx, o);
            if (lane >= o) xx += y;
        }
        wsum[lane] = xx - w;
    }
    __syncthreads();
    int incl = x + wsum[wid];
    if (i < NN) g_rowptr[i] = incl - v;
    if (tid == 511) g_part[blockIdx.x] = incl;
}

__global__ void badd_kernel() {
    __shared__ int parts[SCAN_BLK];
    __shared__ int offs;
    int tid = threadIdx.x;
    if (tid < SCAN_BLK) parts[tid] = g_part[tid];
    __syncthreads();
    if (tid == 0) {
        int o = 0;
        for (int b = 0; b < (int)blockIdx.x; b++) o += parts[b];
        offs = o;
        if (blockIdx.x == gridDim.x - 1) {
            int tot = o;
            for (int b = blockIdx.x; b < SCAN_BLK; b++) tot += parts[b];
            g_rowptr[NN] = tot;
        }
    }
    __syncthreads();
    int i = blockIdx.x * 512 + tid;
    if (i < NN) {
        int r = g_rowptr[i] + offs;
        g_rowptr[i] = r;
        g_cursor[i] = r;
    }
}

__global__ void scatter_kernel(const int* __restrict__ src, const int* __restrict__ dst) {
    int base = (blockIdx.x * blockDim.x + threadIdx.x) * 4;
    if (base + 3 < EE) {
        int4 s4 = *(const int4*)&src[base];
        int4 t4 = *(const int4*)&dst[base];
        int p0 = atomicAdd(&g_cursor[t4.x], 1);
        int p1 = atomicAdd(&g_cursor[t4.y], 1);
        int p2 = atomicAdd(&g_cursor[t4.z], 1);
        int p3 = atomicAdd(&g_cursor[t4.w], 1);
        g_col[p0] = s4.x;
        g_col[p1] = s4.y;
        g_col[p2] = s4.z;
        g_col[p3] = s4.w;
    } else {
        for (int i = base; i < ET && i < base + 4; i++) {
            int s, t;
            if (i < EE) { s = src[i]; t = dst[i]; }
            else        { s = i - EE; t = s; }
            int pos = atomicAdd(&g_cursor[t], 1);
            g_col[pos] = s;
        }
    }
}

// ---------------- W prep: fp32 [k][n] -> fp16 transposed [n][k] ---------------
__global__ void wprep_kernel(const float* __restrict__ W, int layer) {
    int j = blockIdx.x * blockDim.x + threadIdx.x;
    if (j >= DD * DD) return;
    int k = j >> 7, n = j & 127;
    g_Wt[layer * DD * DD + n * DD + k] = __float2half(W[j]);
}

// ---------------- expmap0 (writes fp16 activations) ---------------------------
__global__ void expmap_kernel(const float* __restrict__ x) {
    int gid = blockIdx.x * blockDim.x + threadIdx.x;
    int row = gid >> 5, lane = gid & 31;
    if (row >= NN) return;
    float4 v = ((const float4*)x)[row * 32 + lane];
    float ss = v.x * v.x + v.y * v.y + v.z * v.z + v.w * v.w;
    #pragma unroll
    for (int o = 16; o; o >>= 1) ss += __shfl_xor_sync(0xffffffffu, ss, o);
    float n = sqrtf(ss);
    n = fmaxf(n, 1e-15f);
    float sc = tanhf(n) / n;
    __half2 h0 = __floats2half2_rn(v.x * sc, v.y * sc);
    __half2 h1 = __floats2half2_rn(v.z * sc, v.w * sc);
    uint2 st;
    st.x = *(unsigned int*)&h0;
    st.y = *(unsigned int*)&h1;
    ((uint2*)g_bufA)[row * 32 + lane] = st;
}

// ---------------- tensor-core GEMM: H = A @ W + fused s/d epilogue -----------
// 512 threads (16 warps), tile 128x128. Warp = 16-row slab x 64-col half.
#define KS 136

__device__ __forceinline__ void mma16816(float* c, unsigned a0, unsigned a1,
                                         unsigned a2, unsigned a3,
                                         unsigned b0, unsigned b1) {
    asm volatile(
        "mma.sync.aligned.m16n8k16.row.col.f32.f16.f16.f32 "
        "{%0,%1,%2,%3}, {%4,%5,%6,%7}, {%8,%9}, {%0,%1,%2,%3};"
        : "+f"(c[0]), "+f"(c[1]), "+f"(c[2]), "+f"(c[3])
        : "r"(a0), "r"(a1), "r"(a2), "r"(a3), "r"(b0), "r"(b1));
}

__global__ void __launch_bounds__(512, 2)
gemm_kernel(const __half* __restrict__ A, const __half* __restrict__ Wg,
            const float* __restrict__ avs, const float* __restrict__ avd) {
    extern __shared__ char smraw[];
    __half* Wts = (__half*)smraw;                    // [128][KS]
    __half* As  = Wts + 128 * KS;                    // [128][KS]
    float*  ass = (float*)(As + 128 * KS);           // [128]
    float*  ads = ass + 128;                         // [128]
    float*  sred = ads + 128;                        // [256]
    float*  dred = sred + 256;                       // [256]
    int tid = threadIdx.x;
    int row0 = blockIdx.x * 128;

    for (int i = tid; i < 128 * 16; i += 512) {
        int n = i >> 4, kc = i & 15;
        *(uint4*)&Wts[n * KS + kc * 8] = ((const uint4*)Wg)[i];
    }
    for (int i = tid; i < 128 * 16; i += 512) {
        int r = i >> 4, kc = i & 15;
        int row = row0 + r;
        uint4 v = (row < NN) ? ((const uint4*)A)[row * 16 + kc]
                             : make_uint4(0u, 0u, 0u, 0u);
        *(uint4*)&As[r * KS + kc * 8] = v;
    }
    if (tid < 128) { ass[tid] = avs[tid]; ads[tid] = avd[tid]; }
    __syncthreads();

    int w = tid >> 5, lane = tid & 31;
    int gid = lane >> 2, tig = lane & 3;
    int slab = w >> 1, h = w & 1;
    int rA = slab * 16 + gid;
    int rB = rA + 8;
    int nc0 = h * 64;

    float c[8][4];
    #pragma unroll
    for (int nt = 0; nt < 8; nt++)
        #pragma unroll
        for (int j = 0; j < 4; j++) c[nt][j] = 0.f;

    #pragma unroll
    for (int ks = 0; ks < 8; ks++) {
        int k0 = ks * 16;
        unsigned a0 = *(const unsigned*)&As[rA * KS + k0 + 2 * tig];
        unsigned a1 = *(const unsigned*)&As[rB * KS + k0 + 2 * tig];
        unsigned a2 = *(const unsigned*)&As[rA * KS + k0 + 2 * tig + 8];
        unsigned a3 = *(const unsigned*)&As[rB * KS + k0 + 2 * tig + 8];
        #pragma unroll
        for (int nt = 0; nt < 8; nt++) {
            const __half* bp = &Wts[(nc0 + nt * 8 + gid) * KS + k0 + 2 * tig];
            unsigned b0 = *(const unsigned*)bp;
            unsigned b1 = *(const unsigned*)(bp + 8);
            mma16816(c[nt], a0, a1, a2, a3, b0, b1);
        }
    }

    int rowA = row0 + rA, rowB = row0 + rB;
    float s0 = 0.f, s1 = 0.f, d0 = 0.f, d1 = 0.f;
    #pragma unroll
    for (int nt = 0; nt < 8; nt++) {
        int col = nc0 + nt * 8 + 2 * tig;
        float2 as2 = *(const float2*)&ass[col];
        float2 ad2 = *(const float2*)&ads[col];
        s0 += c[nt][0] * as2.x + c[nt][1] * as2.y;
        d0 += c[nt][0] * ad2.x + c[nt][1] * ad2.y;
        s1 += c[nt][2] * as2.x + c[nt][3] * as2.y;
        d1 += c[nt][2] * ad2.x + c[nt][3] * ad2.y;
        if (rowA < NN) {
            __half2 hh = __floats2half2_rn(c[nt][0], c[nt][1]);
            *(unsigned*)&g_bufH[rowA * 128 + col] = *(unsigned*)&hh;
        }
        if (rowB < NN) {
            __half2 hh = __floats2half2_rn(c[nt][2], c[nt][3]);
            *(unsigned*)&g_bufH[rowB * 128 + col] = *(unsigned*)&hh;
        }
    }
    #pragma unroll
    for (int o = 1; o <= 2; o <<= 1) {
        s0 += __shfl_xor_sync(0xffffffffu, s0, o);
        d0 += __shfl_xor_sync(0xffffffffu, d0, o);
        s1 += __shfl_xor_sync(0xffffffffu, s1, o);
        d1 += __shfl_xor_sync(0xffffffffu, d1, o);
    }
    if (tig == 0) {
        sred[h * 128 + rA] = s0; dred[h * 128 + rA] = d0;
        sred[h * 128 + rB] = s1; dred[h * 128 + rB] = d1;
    }
    __syncthreads();
    if (tid < 128) {
        int row = row0 + tid;
        if (row < NN) {
            g_s[row] = sred[tid] + sred[128 + tid];
            g_d[row] = dred[tid] + dred[128 + tid];
        }
    }
}

// ---------------- per-node attention aggregation: SINGLE PASS ----------------
__global__ void __launch_bounds__(256, 5)
agg_kernel(const __half* __restrict__ H, const float* __restrict__ sarr,
           const float* __restrict__ darr, const float* __restrict__ bias,
           float* __restrict__ outF, __half* __restrict__ outH, int act) {
    int lane = threadIdx.x & 31;
    int node = (blockIdx.x * blockDim.x + threadIdx.x) >> 5;
    if (node >= NN) return;

    int beg = g_rowptr[node], end = g_rowptr[node + 1];
    float di = darr[node];
    int half = lane >> 4, fl = lane & 15;

    float acc8[8];
    #pragma unroll
    for (int q = 0; q < 8; q++) acc8[q] = 0.f;
    float denp = 0.f;

    for (int cb = beg; cb < end; cb += 32) {
        int idx = cb + lane;
        int sn_l = 0;
        float w_l = 0.f;
        if (idx < end) {
            sn_l = g_col[idx];
            float e = __ldg(&sarr[sn_l]) + di;
            e = e > 0.f ? e : 0.2f * e;
            w_l = __expf(e);
        }
        denp += w_l;
        int cn = min(32, end - cb);

        int u = 0;
        for (; u + 8 <= cn; u += 8) {
            uint4 hv[4];
            float al[4];
            #pragma unroll
            for (int p = 0; p < 4; p++) {
                int srcl = u + 2 * p + half;
                int sn = __shfl_sync(0xffffffffu, sn_l, srcl);
                al[p]  = __shfl_sync(0xffffffffu, w_l, srcl);
                hv[p]  = __ldcg(((const uint4*)(H + sn * 128)) + fl);
            }
            #pragma unroll
            for (int p = 0; p < 4; p++) {
                const __half2* hp = (const __half2*)&hv[p];
                #pragma unroll
                for (int q = 0; q < 4; q++) {
                    float2 f = __half22float2(hp[q]);
                    acc8[2 * q + 0] = fmaf(al[p], f.x, acc8[2 * q + 0]);
                    acc8[2 * q + 1] = fmaf(al[p], f.y, acc8[2 * q + 1]);
                }
            }
        }
        for (; u < cn; u += 2) {
            int srcl = u + half;
            int sn  = __shfl_sync(0xffffffffu, sn_l, srcl);
            float al = __shfl_sync(0xffffffffu, w_l, srcl);
            uint4 hv = __ldcg(((const uint4*)(H + sn * 128)) + fl);
            const __half2* hp = (const __half2*)&hv;
            #pragma unroll
            for (int q = 0; q < 4; q++) {
                float2 f = __half22float2(hp[q]);
                acc8[2 * q + 0] = fmaf(al, f.x, acc8[2 * q + 0]);
                acc8[2 * q + 1] = fmaf(al, f.y, acc8[2 * q + 1]);
            }
        }
    }

    #pragma unroll
    for (int o = 16; o; o >>= 1)
        denp += __shfl_xor_sync(0xffffffffu, denp, o);
    #pragma unroll
    for (int q = 0; q < 8; q++)
        acc8[q] += __shfl_xor_sync(0xffffffffu, acc8[q], 16);

    if (half == 0) {
        float inv = 1.f / denp;
        float4 b0 = ((const float4*)bias)[fl * 2];
        float4 b1 = ((const float4*)bias)[fl * 2 + 1];
        acc8[0] = fmaf(acc8[0], inv, b0.x);
        acc8[1] = fmaf(acc8[1], inv, b0.y);
        acc8[2] = fmaf(acc8[2], inv, b0.z);
        acc8[3] = fmaf(acc8[3], inv, b0.w);
        acc8[4] = fmaf(acc8[4], inv, b1.x);
        acc8[5] = fmaf(acc8[5], inv, b1.y);
        acc8[6] = fmaf(acc8[6], inv, b1.z);
        acc8[7] = fmaf(acc8[7], inv, b1.w);
        if (act) {
            #pragma unroll
            for (int q = 0; q < 8; q++) acc8[q] = 2.f * tanhf(acc8[q]);
            __half2 h0 = __floats2half2_rn(acc8[0], acc8[1]);
            __half2 h1 = __floats2half2_rn(acc8[2], acc8[3]);
            __half2 h2 = __floats2half2_rn(acc8[4], acc8[5]);
            __half2 h3 = __floats2half2_rn(acc8[6], acc8[7]);
            uint4 st;
            st.x = *(unsigned*)&h0; st.y = *(unsigned*)&h1;
            st.z = *(unsigned*)&h2; st.w = *(unsigned*)&h3;
            ((uint4*)(outH + node * 128))[fl] = st;
        } else {
            float4 o0 = make_float4(acc8[0], acc8[1], acc8[2], acc8[3]);
            float4 o1 = make_float4(acc8[4], acc8[5], acc8[6], acc8[7]);
            ((float4*)(outF + node * 128))[fl * 2] = o0;
            ((float4*)(outF + node * 128))[fl * 2 + 1] = o1;
        }
    }
}

// ---------------- launch ------------------------------------------------------
extern "C" void kernel_launch(void* const* d_in, const int* in_sizes, int n_in,
                              void* d_out, int out_size) {
    const float* x   = (const float*)d_in[0];
    const int*   ei  = (const int*)d_in[1];
    const int*   esrc = ei;
    const int*   edst = ei + EE;
    const float* W1  = (const float*)d_in[2];
    const float* a1s = (const float*)d_in[3];
    const float* a1d = (const float*)d_in[4];
    const float* b1  = (const float*)d_in[5];
    const float* W2  = (const float*)d_in[6];
    const float* a2s = (const float*)d_in[7];
    const float* a2d = (const float*)d_in[8];
    const float* b2  = (const float*)d_in[9];
    const float* W3  = (const float*)d_in[10];
    const float* a3s = (const float*)d_in[11];
    const float* a3d = (const float*)d_in[12];
    const float* b3  = (const float*)d_in[13];
    float* out = (float*)d_out;

    float *pS, *pD;
    __half *pA, *pH, *pW;
    cudaGetSymbolAddress((void**)&pA, g_bufA);
    cudaGetSymbolAddress((void**)&pH, g_bufH);
    cudaGetSymbolAddress((void**)&pW, g_Wt);
    cudaGetSymbolAddress((void**)&pS, g_s);
    cudaGetSymbolAddress((void**)&pD, g_d);

    const int SMEM = (128 * KS + 128 * KS) * 2 + 2 * 128 * 4 + 2 * 256 * 4; // ~72.7 KB
    cudaFuncSetAttribute(gemm_kernel, cudaFuncAttributeMaxDynamicSharedMemorySize, SMEM);

    // side stream + events for CSR || layer-1 compute (host objects only)
    static cudaStream_t s1 = nullptr;
    static cudaEvent_t eFork = nullptr, eJoin = nullptr;
    if (!s1) {
        cudaStreamCreateWithFlags(&s1, cudaStreamNonBlocking);
        cudaEventCreateWithFlags(&eFork, cudaEventDisableTiming);
        cudaEventCreateWithFlags(&eJoin, cudaEventDisableTiming);
    }

    int gemm_blocks = (NN + 127) / 128;      // 391
    int agg_blocks  = (NN + 7) / 8;
    int wblocks = (DD * DD + 255) / 256;
    int hist_blocks = (EE / 4 + 255) / 256;
    int scat_blocks = ((ET + 3) / 4 + 255) / 256;

    // fork: CSR build on s1, concurrent with expmap+wprep+gemm1 on stream 0
    cudaEventRecord(eFork, 0);
    cudaStreamWaitEvent(s1, eFork, 0);

    init_count_kernel<<<(NN + 255) / 256, 256, 0, s1>>>();
    hist_kernel<<<hist_blocks, 256, 0, s1>>>(edst);
    bscan_kernel<<<SCAN_BLK, 512, 0, s1>>>();
    badd_kernel<<<SCAN_BLK, 512, 0, s1>>>();
    scatter_kernel<<<scat_blocks, 256, 0, s1>>>(esrc, edst);
    cudaEventRecord(eJoin, s1);

    expmap_kernel<<<(NN * 32 + 255) / 256, 256>>>(x);
    wprep_kernel<<<wblocks, 256>>>(W1, 0);
    wprep_kernel<<<wblocks, 256>>>(W2, 1);
    wprep_kernel<<<wblocks, 256>>>(W3, 2);
    gemm_kernel<<<gemm_blocks, 512, SMEM>>>(pA, pW, a1s, a1d);

    // join: agg1 needs both CSR and gemm1
    cudaStreamWaitEvent(0, eJoin, 0);

    agg_kernel<<<agg_blocks, 256>>>(pH, pS, pD, b1, nullptr, pA, 1);
    gemm_kernel<<<gemm_blocks, 512, SMEM>>>(pA, pW + DD * DD, a2s, a2d);
    agg_kernel<<<agg_blocks, 256>>>(pH, pS, pD, b2, nullptr, pA, 1);
    gemm_kernel<<<gemm_blocks, 512, SMEM>>>(pA, pW + 2 * DD * DD, a3s, a3d);
    agg_kernel<<<agg_blocks, 256>>>(pH, pS, pD, b3, out, nullptr, 0);
}